// round 12
// baseline (speedup 1.0000x reference)
#include <cuda_runtime.h>
#include <math.h>

#define B_ 512
#define C_ 64
#define H_ 128
#define P_ 16
#define G_ 2
#define EPS_ 1e-5f

typedef unsigned long long u64;

__device__ __forceinline__ u64 fma2(u64 a, u64 b, u64 c) {
    u64 d;
    asm("fma.rn.f32x2 %0, %1, %2, %3;" : "=l"(d) : "l"(a), "l"(b), "l"(c));
    return d;
}
__device__ __forceinline__ u64 pack2(float lo, float hi) {
    u64 d; asm("mov.b64 %0, {%1, %2};" : "=l"(d) : "f"(lo), "f"(hi)); return d;
}
__device__ __forceinline__ float2 unpack2(u64 v) {
    float2 r; asm("mov.b64 {%0, %1}, %2;" : "=f"(r.x), "=f"(r.y) : "l"(v)); return r;
}

// ---------------- device scratch ----------------
__device__ float  g_F[C_ * H_];       // F[c][k] = ec[c][k] + sum_h W2[h][k]*ec[c][h]
__device__ float  g_hpc[P_ * C_];     // hpc[p][c]
__device__ float4 g_pc[P_];           // {|w|, max(-w,0), gn_w, gn_b}
__device__ float  g_gc[2 * 4];        // per-group {A1,A2,B1,B2}

// ---------------- K1: setup kernel (64 blocks = c, 256 threads) ----------------
__global__ __launch_bounds__(256)
void setup_kernel(const float* __restrict__ emb_column,
                  const float* __restrict__ emb_prompt,
                  const float* __restrict__ lin_w,
                  const float* __restrict__ lin_b,
                  const float* __restrict__ ln_col_w,
                  const float* __restrict__ ln_col_b,
                  const float* __restrict__ ln_pr_w,
                  const float* __restrict__ ln_pr_b,
                  const float* __restrict__ expand_weight,
                  const float* __restrict__ gn_w,
                  const float* __restrict__ gn_b)
{
    __shared__ float s_ec[H_];
    __shared__ float s_ep[P_][H_];
    __shared__ float s_G1[H_];

    const int c    = blockIdx.x;
    const int tid  = threadIdx.x;
    const int warp = tid >> 5;
    const int lane = tid & 31;

    if (warp == 0) {
        const float* src = emb_column + c * H_;
        float v[4]; float s = 0.f, ss = 0.f;
        #pragma unroll
        for (int i = 0; i < 4; i++) { v[i] = src[lane + 32 * i]; s += v[i]; ss += v[i] * v[i]; }
        #pragma unroll
        for (int o = 16; o > 0; o >>= 1) {
            s  += __shfl_xor_sync(0xffffffffu, s,  o);
            ss += __shfl_xor_sync(0xffffffffu, ss, o);
        }
        const float mu  = s * (1.f / H_);
        const float inv = rsqrtf(ss * (1.f / H_) - mu * mu + EPS_);
        #pragma unroll
        for (int i = 0; i < 4; i++) {
            const int hh = lane + 32 * i;
            s_ec[hh] = (v[i] - mu) * inv * ln_col_w[hh] + ln_col_b[hh];
        }
    }
    #pragma unroll
    for (int rr = 0; rr < 2; rr++) {
        const int r = warp + rr * 8;
        const float* src = emb_prompt + r * H_;
        float v[4]; float s = 0.f, ss = 0.f;
        #pragma unroll
        for (int i = 0; i < 4; i++) { v[i] = src[lane + 32 * i]; s += v[i]; ss += v[i] * v[i]; }
        #pragma unroll
        for (int o = 16; o > 0; o >>= 1) {
            s  += __shfl_xor_sync(0xffffffffu, s,  o);
            ss += __shfl_xor_sync(0xffffffffu, ss, o);
        }
        const float mu  = s * (1.f / H_);
        const float inv = rsqrtf(ss * (1.f / H_) - mu * mu + EPS_);
        #pragma unroll
        for (int i = 0; i < 4; i++) {
            const int hh = lane + 32 * i;
            s_ep[r][hh] = (v[i] - mu) * inv * ln_pr_w[hh] + ln_pr_b[hh];
        }
    }
    __syncthreads();

    // G1 / F with deep unroll (MLP=16)
    {
        const int k     = tid & 127;
        const int which = tid >> 7;
        const float* base = lin_w + which * H_ + k;
        float acc = 0.f;
        #pragma unroll
        for (int hb = 0; hb < H_; hb += 16) {
            float w[16];
            #pragma unroll
            for (int i = 0; i < 16; i++)
                w[i] = base[(hb + i) * (2 * H_)];
            #pragma unroll
            for (int i = 0; i < 16; i++)
                acc += w[i] * s_ec[hb + i];
        }
        if (which == 0) s_G1[k] = acc;
        else            g_F[c * H_ + k] = acc + s_ec[k];
    }
    __syncthreads();

    #pragma unroll
    for (int rr = 0; rr < 2; rr++) {
        const int p = warp + rr * 8;
        float a = 0.f;
        #pragma unroll
        for (int i = 0; i < 4; i++) {
            const int hh = lane + 32 * i;
            const float e = s_ep[p][hh];
            a += (lin_b[hh] + e) * s_ec[hh] + e * s_G1[hh];
        }
        #pragma unroll
        for (int o = 16; o > 0; o >>= 1)
            a += __shfl_xor_sync(0xffffffffu, a, o);
        if (lane == 0) g_hpc[p * C_ + c] = a;
    }

    if (c == 0 && tid == 0) {
        #pragma unroll
        for (int p = 0; p < P_; p++) {
            const float w = expand_weight[p];
            g_pc[p] = make_float4(fabsf(w), fmaxf(-w, 0.f), gn_w[p], gn_b[p]);
        }
        for (int g = 0; g < 2; g++) {
            float A1 = 0.f, A2 = 0.f, B1 = 0.f, B2 = 0.f;
            for (int p = g * 8; p < g * 8 + 8; p++) {
                const float w  = expand_weight[p];
                const float aw = fabsf(w);
                const float v  = fmaxf(-w, 0.f);
                const float u  = aw - v;
                A1 += aw; A2 += v; B1 += u * u; B2 += v * v;
            }
            g_gc[g * 4 + 0] = A1; g_gc[g * 4 + 1] = A2;
            g_gc[g * 4 + 2] = B1; g_gc[g * 4 + 3] = B2;
        }
    }
}

// ---------------- K2: fused per-batch kernel (512 blocks, 256 threads, 4/SM) --------
// smem (floats): F[64x132] | m[16][64] | mt[64x20] | red[16] | grp[8]
#define SM_F     0                        // 8448
#define SM_M     (64 * 132)               // 1024
#define SM_MT    (SM_M + 16 * 64)         // 1280
#define SM_RED   (SM_MT + 64 * 20)        // 16
#define SM_GRP   (SM_RED + 16)            // 8
#define SM_FLOATS (SM_GRP + 8)            // 10776 floats = 43,104 B

extern __shared__ float sm[];

__global__ void __launch_bounds__(256, 4)
trompt_main_kernel(const float* __restrict__ x,
                   const float* __restrict__ x_prompt,
                   float* __restrict__ out)
{
    float* s_F   = sm + SM_F;
    float* s_m   = sm + SM_M;
    float* s_mt  = sm + SM_MT;
    float* s_red = sm + SM_RED;
    float* s_grp = sm + SM_GRP;

    const int tid  = threadIdx.x;
    const int b    = blockIdx.x;
    const int warp = tid >> 5;
    const int lane = tid & 31;
    const float* xb = x + (size_t)b * (C_ * H_);

    // ---- F staging only (stats fused into phase 4)
    {
        const float4* f4 = (const float4*)g_F;
        #pragma unroll
        for (int i = 0; i < 8; i++) {
            const int e = tid + i * 256;
            const float4 v = f4[e];
            const int idx = e * 4;
            *(float4*)(s_F + (idx >> 7) * 132 + (idx & 127)) = v;
        }
    }
    __syncthreads();

    // ---- phase M: m[p,c] = hpc + xp @ F^T ; thread = (c, pg of 4p); pipelined e
    {
        const int c  = tid & 63;
        const int pg = tid >> 6;     // 0..3
        const int p0 = pg * 4;
        const float* xpg = x_prompt + (size_t)b * (P_ * H_);
        u64 acc[4] = {0,0,0,0}, accB[4] = {0,0,0,0};
        ulonglong2 e = *(const ulonglong2*)(s_F + c * 132);
        #pragma unroll 4
        for (int hh = 0; hh < H_ - 4; hh += 4) {
            const ulonglong2 en = *(const ulonglong2*)(s_F + c * 132 + hh + 4);
            #pragma unroll
            for (int j = 0; j < 4; j++) {
                const ulonglong2 t = *(const ulonglong2*)(xpg + (p0 + j) * H_ + hh);
                acc[j]  = fma2(e.x, t.x, acc[j]);
                accB[j] = fma2(e.y, t.y, accB[j]);
            }
            e = en;
        }
        #pragma unroll
        for (int j = 0; j < 4; j++) {
            const ulonglong2 t = *(const ulonglong2*)(xpg + (p0 + j) * H_ + (H_ - 4));
            acc[j]  = fma2(e.x, t.x, acc[j]);
            accB[j] = fma2(e.y, t.y, accB[j]);
        }
        #pragma unroll
        for (int j = 0; j < 4; j++) {
            const float2 r  = unpack2(acc[j]);
            const float2 r2 = unpack2(accB[j]);
            s_m[(p0 + j) * 64 + c] = (r.x + r.y) + (r2.x + r2.y) + g_hpc[(p0 + j) * C_ + c];
        }
    }
    __syncthreads();

    // ---- softmax: warp w handles p = w, w+8; transposed store to s_mt
    #pragma unroll
    for (int rr = 0; rr < 2; rr++) {
        const int p = warp + rr * 8;
        const float v0 = s_m[p * 64 + lane];
        const float v1 = s_m[p * 64 + 32 + lane];
        float mx = fmaxf(v0, v1);
        #pragma unroll
        for (int o = 16; o > 0; o >>= 1)
            mx = fmaxf(mx, __shfl_xor_sync(0xffffffffu, mx, o));
        const float e0 = __expf(v0 - mx);
        const float e1 = __expf(v1 - mx);
        float s = e0 + e1;
        #pragma unroll
        for (int o = 16; o > 0; o >>= 1)
            s += __shfl_xor_sync(0xffffffffu, s, o);
        const float inv = 1.f / s;
        s_mt[lane * 20 + p]        = e0 * inv;
        s_mt[(lane + 32) * 20 + p] = e1 * inv;
    }
    __syncthreads();

    // ---- phase 4: accumulate Rm/Xm (+ fused stats on pb==0); software-pipelined
    const int h  = tid & 127;
    const int pb = tid >> 7;     // 0..1, p = pb*8 + j; warp-uniform
    u64 aR[4] = {0,0,0,0}, aX[4] = {0,0,0,0};
    {
        float s1 = 0.f, sx = 0.f, sr2 = 0.f, sx2 = 0.f;
        const float* xcol = xb + h;
        const float* mrow = s_mt + pb * 8;
        ulonglong2 m01 = *(const ulonglong2*)(mrow);
        ulonglong2 m23 = *(const ulonglong2*)(mrow + 4);
        float xv = xcol[0];
        #pragma unroll 4
        for (int c = 0; c < C_ - 1; c++) {
            const ulonglong2 n01 = *(const ulonglong2*)(mrow + (c + 1) * 20);
            const ulonglong2 n23 = *(const ulonglong2*)(mrow + (c + 1) * 20 + 4);
            const float xn = xcol[(c + 1) * H_];
            const float rv = fmaxf(xv, 0.f);
            const u64 rr = pack2(rv, rv);
            const u64 xx = pack2(xv, xv);
            aR[0] = fma2(m01.x, rr, aR[0]);
            aR[1] = fma2(m01.y, rr, aR[1]);
            aR[2] = fma2(m23.x, rr, aR[2]);
            aR[3] = fma2(m23.y, rr, aR[3]);
            aX[0] = fma2(m01.x, xx, aX[0]);
            aX[1] = fma2(m01.y, xx, aX[1]);
            aX[2] = fma2(m23.x, xx, aX[2]);
            aX[3] = fma2(m23.y, xx, aX[3]);
            if (pb == 0) { s1 += rv; sx += xv; sr2 += rv * rv; sx2 += xv * xv; }
            m01 = n01; m23 = n23; xv = xn;
        }
        {   // epilogue c = 63
            const float rv = fmaxf(xv, 0.f);
            const u64 rr = pack2(rv, rv);
            const u64 xx = pack2(xv, xv);
            aR[0] = fma2(m01.x, rr, aR[0]);
            aR[1] = fma2(m01.y, rr, aR[1]);
            aR[2] = fma2(m23.x, rr, aR[2]);
            aR[3] = fma2(m23.y, rr, aR[3]);
            aX[0] = fma2(m01.x, xx, aX[0]);
            aX[1] = fma2(m01.y, xx, aX[1]);
            aX[2] = fma2(m23.x, xx, aX[2]);
            aX[3] = fma2(m23.y, xx, aX[3]);
            if (pb == 0) { s1 += rv; sx += xv; sr2 += rv * rv; sx2 += xv * xv; }
        }
        if (pb == 0) {
            #pragma unroll
            for (int o = 16; o > 0; o >>= 1) {
                s1  += __shfl_xor_sync(0xffffffffu, s1,  o);
                sx  += __shfl_xor_sync(0xffffffffu, sx,  o);
                sr2 += __shfl_xor_sync(0xffffffffu, sr2, o);
                sx2 += __shfl_xor_sync(0xffffffffu, sx2, o);
            }
            if (lane == 0) {
                s_red[warp * 4 + 0] = s1;  s_red[warp * 4 + 1] = sx;
                s_red[warp * 4 + 2] = sr2; s_red[warp * 4 + 3] = sx2;
            }
        }
    }
    __syncthreads();

    if (tid == 0) {
        float S1 = 0.f, Sx = 0.f, Sr2 = 0.f, Sx2 = 0.f;
        #pragma unroll
        for (int w = 0; w < 4; w++) {
            S1 += s_red[w * 4 + 0]; Sx  += s_red[w * 4 + 1];
            Sr2 += s_red[w * 4 + 2]; Sx2 += s_red[w * 4 + 3];
        }
        const float invN = 1.f / 65536.f;
        #pragma unroll
        for (int g = 0; g < 2; g++) {
            const float A1 = g_gc[g * 4 + 0], A2 = g_gc[g * 4 + 1];
            const float B1 = g_gc[g * 4 + 2], B2 = g_gc[g * 4 + 3];
            const float mu = (A1 * S1 - A2 * Sx) * invN;
            const float E2 = (B1 * Sr2 + B2 * (Sx2 - Sr2)) * invN;
            s_grp[g * 2 + 0] = mu;
            s_grp[g * 2 + 1] = rsqrtf(E2 - mu * mu + EPS_);
        }
    }
    __syncthreads();

    // ---- apply coefficients + store
    {
        float* ob = out + (size_t)b * (P_ * H_);
        #pragma unroll
        for (int q = 0; q < 4; q++) {
            const float2 R = unpack2(aR[q]);
            const float2 X = unpack2(aX[q]);
            #pragma unroll
            for (int half = 0; half < 2; half++) {
                const int p = pb * 8 + q * 2 + half;
                const float4 pc = g_pc[p];
                const int g = p >> 3;
                const float mu = s_grp[g * 2 + 0];
                const float rs = s_grp[g * 2 + 1];
                const float gr = pc.z * rs;
                const float c1 = gr * pc.x;
                const float c2 = 1.f - gr * pc.y;
                const float c3 = pc.w - gr * mu;
                const float Rv = half ? R.y : R.x;
                const float Xv = half ? X.y : X.x;
                ob[p * H_ + h] = c1 * Rv + c2 * Xv + c3;
            }
        }
    }
}

// ---------------- launch ----------------
extern "C" void kernel_launch(void* const* d_in, const int* in_sizes, int n_in,
                              void* d_out, int out_size)
{
    const float* x          = (const float*)d_in[0];
    const float* x_prompt   = (const float*)d_in[1];
    const float* emb_column = (const float*)d_in[2];
    const float* emb_prompt = (const float*)d_in[3];
    const float* lin_w      = (const float*)d_in[4];
    const float* lin_b      = (const float*)d_in[5];
    const float* ln_col_w   = (const float*)d_in[6];
    const float* ln_col_b   = (const float*)d_in[7];
    const float* ln_pr_w    = (const float*)d_in[8];
    const float* ln_pr_b    = (const float*)d_in[9];
    const float* expand_w   = (const float*)d_in[10];
    const float* gn_w       = (const float*)d_in[11];
    const float* gn_b       = (const float*)d_in[12];
    float* out = (float*)d_out;

    const int smemBytes = SM_FLOATS * (int)sizeof(float);   // 43,104 B
    cudaFuncSetAttribute(trompt_main_kernel,
                         cudaFuncAttributeMaxDynamicSharedMemorySize, smemBytes);

    setup_kernel<<<64, 256>>>(emb_column, emb_prompt, lin_w, lin_b,
                              ln_col_w, ln_col_b, ln_pr_w, ln_pr_b,
                              expand_w, gn_w, gn_b);
    trompt_main_kernel<<<B_, 256, smemBytes>>>(x, x_prompt, out);
}

// round 13
// speedup vs baseline: 1.0749x; 1.0749x over previous
#include <cuda_runtime.h>
#include <math.h>

#define B_ 512
#define C_ 64
#define H_ 128
#define P_ 16
#define G_ 2
#define EPS_ 1e-5f

typedef unsigned long long u64;

__device__ __forceinline__ u64 fma2(u64 a, u64 b, u64 c) {
    u64 d;
    asm("fma.rn.f32x2 %0, %1, %2, %3;" : "=l"(d) : "l"(a), "l"(b), "l"(c));
    return d;
}
__device__ __forceinline__ u64 pack2(float lo, float hi) {
    u64 d; asm("mov.b64 %0, {%1, %2};" : "=l"(d) : "f"(lo), "f"(hi)); return d;
}
__device__ __forceinline__ float2 unpack2(u64 v) {
    float2 r; asm("mov.b64 {%0, %1}, %2;" : "=f"(r.x), "=f"(r.y) : "l"(v)); return r;
}

// ---------------- device scratch ----------------
__device__ float  g_F[C_ * H_];       // F[c][k] = ec[c][k] + sum_h W2[h][k]*ec[c][h]
__device__ float  g_hpc[P_ * C_];     // hpc[p][c]
__device__ float4 g_pc[P_];           // {|w|, max(-w,0), gn_w, gn_b}
__device__ float  g_gc[2 * 4];        // per-group {A1,A2,B1,B2}

// ---------------- K1: setup kernel (64 blocks = c, 256 threads) ----------------
__global__ __launch_bounds__(256)
void setup_kernel(const float* __restrict__ emb_column,
                  const float* __restrict__ emb_prompt,
                  const float* __restrict__ lin_w,
                  const float* __restrict__ lin_b,
                  const float* __restrict__ ln_col_w,
                  const float* __restrict__ ln_col_b,
                  const float* __restrict__ ln_pr_w,
                  const float* __restrict__ ln_pr_b,
                  const float* __restrict__ expand_weight,
                  const float* __restrict__ gn_w,
                  const float* __restrict__ gn_b)
{
    __shared__ float s_ec[H_];
    __shared__ float s_ep[P_][H_];
    __shared__ float s_G1[H_];

    const int c    = blockIdx.x;
    const int tid  = threadIdx.x;
    const int warp = tid >> 5;
    const int lane = tid & 31;

    if (warp == 0) {
        const float* src = emb_column + c * H_;
        float v[4]; float s = 0.f, ss = 0.f;
        #pragma unroll
        for (int i = 0; i < 4; i++) { v[i] = src[lane + 32 * i]; s += v[i]; ss += v[i] * v[i]; }
        #pragma unroll
        for (int o = 16; o > 0; o >>= 1) {
            s  += __shfl_xor_sync(0xffffffffu, s,  o);
            ss += __shfl_xor_sync(0xffffffffu, ss, o);
        }
        const float mu  = s * (1.f / H_);
        const float inv = rsqrtf(ss * (1.f / H_) - mu * mu + EPS_);
        #pragma unroll
        for (int i = 0; i < 4; i++) {
            const int hh = lane + 32 * i;
            s_ec[hh] = (v[i] - mu) * inv * ln_col_w[hh] + ln_col_b[hh];
        }
    }
    #pragma unroll
    for (int rr = 0; rr < 2; rr++) {
        const int r = warp + rr * 8;
        const float* src = emb_prompt + r * H_;
        float v[4]; float s = 0.f, ss = 0.f;
        #pragma unroll
        for (int i = 0; i < 4; i++) { v[i] = src[lane + 32 * i]; s += v[i]; ss += v[i] * v[i]; }
        #pragma unroll
        for (int o = 16; o > 0; o >>= 1) {
            s  += __shfl_xor_sync(0xffffffffu, s,  o);
            ss += __shfl_xor_sync(0xffffffffu, ss, o);
        }
        const float mu  = s * (1.f / H_);
        const float inv = rsqrtf(ss * (1.f / H_) - mu * mu + EPS_);
        #pragma unroll
        for (int i = 0; i < 4; i++) {
            const int hh = lane + 32 * i;
            s_ep[r][hh] = (v[i] - mu) * inv * ln_pr_w[hh] + ln_pr_b[hh];
        }
    }
    __syncthreads();

    // G1 / F with deep unroll (MLP=16)
    {
        const int k     = tid & 127;
        const int which = tid >> 7;
        const float* base = lin_w + which * H_ + k;
        float acc = 0.f;
        #pragma unroll
        for (int hb = 0; hb < H_; hb += 16) {
            float w[16];
            #pragma unroll
            for (int i = 0; i < 16; i++)
                w[i] = base[(hb + i) * (2 * H_)];
            #pragma unroll
            for (int i = 0; i < 16; i++)
                acc += w[i] * s_ec[hb + i];
        }
        if (which == 0) s_G1[k] = acc;
        else            g_F[c * H_ + k] = acc + s_ec[k];
    }
    __syncthreads();

    #pragma unroll
    for (int rr = 0; rr < 2; rr++) {
        const int p = warp + rr * 8;
        float a = 0.f;
        #pragma unroll
        for (int i = 0; i < 4; i++) {
            const int hh = lane + 32 * i;
            const float e = s_ep[p][hh];
            a += (lin_b[hh] + e) * s_ec[hh] + e * s_G1[hh];
        }
        #pragma unroll
        for (int o = 16; o > 0; o >>= 1)
            a += __shfl_xor_sync(0xffffffffu, a, o);
        if (lane == 0) g_hpc[p * C_ + c] = a;
    }

    if (c == 0 && tid == 0) {
        #pragma unroll
        for (int p = 0; p < P_; p++) {
            const float w = expand_weight[p];
            g_pc[p] = make_float4(fabsf(w), fmaxf(-w, 0.f), gn_w[p], gn_b[p]);
        }
        for (int g = 0; g < 2; g++) {
            float A1 = 0.f, A2 = 0.f, B1 = 0.f, B2 = 0.f;
            for (int p = g * 8; p < g * 8 + 8; p++) {
                const float w  = expand_weight[p];
                const float aw = fabsf(w);
                const float v  = fmaxf(-w, 0.f);
                const float u  = aw - v;
                A1 += aw; A2 += v; B1 += u * u; B2 += v * v;
            }
            g_gc[g * 4 + 0] = A1; g_gc[g * 4 + 1] = A2;
            g_gc[g * 4 + 2] = B1; g_gc[g * 4 + 3] = B2;
        }
    }
}

// ---------------- K2: fused per-batch kernel (512 blocks, 256 threads, 5/SM) --------
// smem (floats): F[64x132] | m[16][64] | mt[64x20] | red[16] | grp[8]
#define SM_F     0                        // 8448
#define SM_M     (64 * 132)               // 1024
#define SM_MT    (SM_M + 16 * 64)         // 1280
#define SM_RED   (SM_MT + 64 * 20)        // 16
#define SM_GRP   (SM_RED + 16)            // 8
#define SM_FLOATS (SM_GRP + 8)            // 10776 floats = 43,104 B

extern __shared__ float sm[];

__global__ void __launch_bounds__(256, 5)
trompt_main_kernel(const float* __restrict__ x,
                   const float* __restrict__ x_prompt,
                   float* __restrict__ out)
{
    float* s_F   = sm + SM_F;
    float* s_m   = sm + SM_M;
    float* s_mt  = sm + SM_MT;
    float* s_red = sm + SM_RED;
    float* s_grp = sm + SM_GRP;

    const int tid  = threadIdx.x;
    const int b    = blockIdx.x;
    const int warp = tid >> 5;
    const int lane = tid & 31;
    const float* xb = x + (size_t)b * (C_ * H_);

    // ---- F staging only (stats fused into phase 4)
    {
        const float4* f4 = (const float4*)g_F;
        #pragma unroll
        for (int i = 0; i < 8; i++) {
            const int e = tid + i * 256;
            const float4 v = f4[e];
            const int idx = e * 4;
            *(float4*)(s_F + (idx >> 7) * 132 + (idx & 127)) = v;
        }
    }
    __syncthreads();

    // ---- phase M: m[p,c] = hpc + xp @ F^T ; thread = (c, pg of 4p), full h loop
    {
        const int c  = tid & 63;
        const int pg = tid >> 6;     // 0..3
        const int p0 = pg * 4;
        const float* xpg = x_prompt + (size_t)b * (P_ * H_);
        u64 acc[4] = {0,0,0,0}, accB[4] = {0,0,0,0};
        #pragma unroll 8
        for (int hh = 0; hh < H_; hh += 4) {
            const ulonglong2 e = *(const ulonglong2*)(s_F + c * 132 + hh);
            #pragma unroll
            for (int j = 0; j < 4; j++) {
                const ulonglong2 t = *(const ulonglong2*)(xpg + (p0 + j) * H_ + hh);
                acc[j]  = fma2(e.x, t.x, acc[j]);
                accB[j] = fma2(e.y, t.y, accB[j]);
            }
        }
        #pragma unroll
        for (int j = 0; j < 4; j++) {
            const float2 r  = unpack2(acc[j]);
            const float2 r2 = unpack2(accB[j]);
            s_m[(p0 + j) * 64 + c] = (r.x + r.y) + (r2.x + r2.y) + g_hpc[(p0 + j) * C_ + c];
        }
    }
    __syncthreads();

    // ---- softmax: warp w handles p = w, w+8; transposed store to s_mt
    #pragma unroll
    for (int rr = 0; rr < 2; rr++) {
        const int p = warp + rr * 8;
        const float v0 = s_m[p * 64 + lane];
        const float v1 = s_m[p * 64 + 32 + lane];
        float mx = fmaxf(v0, v1);
        #pragma unroll
        for (int o = 16; o > 0; o >>= 1)
            mx = fmaxf(mx, __shfl_xor_sync(0xffffffffu, mx, o));
        const float e0 = __expf(v0 - mx);
        const float e1 = __expf(v1 - mx);
        float s = e0 + e1;
        #pragma unroll
        for (int o = 16; o > 0; o >>= 1)
            s += __shfl_xor_sync(0xffffffffu, s, o);
        const float inv = 1.f / s;
        s_mt[lane * 20 + p]        = e0 * inv;
        s_mt[(lane + 32) * 20 + p] = e1 * inv;
    }
    __syncthreads();

    // ---- phase 4: accumulate Rm/Xm (+ fused stats on pb==0); thread = (h, pb of 8p)
    const int h  = tid & 127;
    const int pb = tid >> 7;     // 0..1, p = pb*8 + j; warp-uniform
    u64 aR[4] = {0,0,0,0}, aX[4] = {0,0,0,0};
    {
        float s1 = 0.f, sx = 0.f, sr2 = 0.f, sx2 = 0.f;
        #pragma unroll 8
        for (int c = 0; c < C_; c++) {
            const float xv = xb[c * H_ + h];
            const float rv = fmaxf(xv, 0.f);
            const u64 rr = pack2(rv, rv);
            const u64 xx = pack2(xv, xv);
            const ulonglong2 m01 = *(const ulonglong2*)(s_mt + c * 20 + pb * 8);
            const ulonglong2 m23 = *(const ulonglong2*)(s_mt + c * 20 + pb * 8 + 4);
            aR[0] = fma2(m01.x, rr, aR[0]);
            aR[1] = fma2(m01.y, rr, aR[1]);
            aR[2] = fma2(m23.x, rr, aR[2]);
            aR[3] = fma2(m23.y, rr, aR[3]);
            aX[0] = fma2(m01.x, xx, aX[0]);
            aX[1] = fma2(m01.y, xx, aX[1]);
            aX[2] = fma2(m23.x, xx, aX[2]);
            aX[3] = fma2(m23.y, xx, aX[3]);
            if (pb == 0) {            // warp-uniform predicate; each (c,h) counted once
                s1 += rv; sx += xv; sr2 += rv * rv; sx2 += xv * xv;
            }
        }
        if (pb == 0) {
            #pragma unroll
            for (int o = 16; o > 0; o >>= 1) {
                s1  += __shfl_xor_sync(0xffffffffu, s1,  o);
                sx  += __shfl_xor_sync(0xffffffffu, sx,  o);
                sr2 += __shfl_xor_sync(0xffffffffu, sr2, o);
                sx2 += __shfl_xor_sync(0xffffffffu, sx2, o);
            }
            if (lane == 0) {
                s_red[warp * 4 + 0] = s1;  s_red[warp * 4 + 1] = sx;
                s_red[warp * 4 + 2] = sr2; s_red[warp * 4 + 3] = sx2;
            }
        }
    }
    __syncthreads();

    if (tid == 0) {
        float S1 = 0.f, Sx = 0.f, Sr2 = 0.f, Sx2 = 0.f;
        #pragma unroll
        for (int w = 0; w < 4; w++) {
            S1 += s_red[w * 4 + 0]; Sx  += s_red[w * 4 + 1];
            Sr2 += s_red[w * 4 + 2]; Sx2 += s_red[w * 4 + 3];
        }
        const float invN = 1.f / 65536.f;
        #pragma unroll
        for (int g = 0; g < 2; g++) {
            const float A1 = g_gc[g * 4 + 0], A2 = g_gc[g * 4 + 1];
            const float B1 = g_gc[g * 4 + 2], B2 = g_gc[g * 4 + 3];
            const float mu = (A1 * S1 - A2 * Sx) * invN;
            const float E2 = (B1 * Sr2 + B2 * (Sx2 - Sr2)) * invN;
            s_grp[g * 2 + 0] = mu;
            s_grp[g * 2 + 1] = rsqrtf(E2 - mu * mu + EPS_);
        }
    }
    __syncthreads();

    // ---- apply coefficients + store
    {
        float* ob = out + (size_t)b * (P_ * H_);
        #pragma unroll
        for (int q = 0; q < 4; q++) {
            const float2 R = unpack2(aR[q]);
            const float2 X = unpack2(aX[q]);
            #pragma unroll
            for (int half = 0; half < 2; half++) {
                const int p = pb * 8 + q * 2 + half;
                const float4 pc = g_pc[p];
                const int g = p >> 3;
                const float mu = s_grp[g * 2 + 0];
                const float rs = s_grp[g * 2 + 1];
                const float gr = pc.z * rs;
                const float c1 = gr * pc.x;
                const float c2 = 1.f - gr * pc.y;
                const float c3 = pc.w - gr * mu;
                const float Rv = half ? R.y : R.x;
                const float Xv = half ? X.y : X.x;
                ob[p * H_ + h] = c1 * Rv + c2 * Xv + c3;
            }
        }
    }
}

// ---------------- launch ----------------
extern "C" void kernel_launch(void* const* d_in, const int* in_sizes, int n_in,
                              void* d_out, int out_size)
{
    const float* x          = (const float*)d_in[0];
    const float* x_prompt   = (const float*)d_in[1];
    const float* emb_column = (const float*)d_in[2];
    const float* emb_prompt = (const float*)d_in[3];
    const float* lin_w      = (const float*)d_in[4];
    const float* lin_b      = (const float*)d_in[5];
    const float* ln_col_w   = (const float*)d_in[6];
    const float* ln_col_b   = (const float*)d_in[7];
    const float* ln_pr_w    = (const float*)d_in[8];
    const float* ln_pr_b    = (const float*)d_in[9];
    const float* expand_w   = (const float*)d_in[10];
    const float* gn_w       = (const float*)d_in[11];
    const float* gn_b       = (const float*)d_in[12];
    float* out = (float*)d_out;

    const int smemBytes = SM_FLOATS * (int)sizeof(float);   // 43,104 B
    cudaFuncSetAttribute(trompt_main_kernel,
                         cudaFuncAttributeMaxDynamicSharedMemorySize, smemBytes);

    setup_kernel<<<64, 256>>>(emb_column, emb_prompt, lin_w, lin_b,
                              ln_col_w, ln_col_b, ln_pr_w, ln_pr_b,
                              expand_w, gn_w, gn_b);
    trompt_main_kernel<<<B_, 256, smemBytes>>>(x, x_prompt, out);
}